// round 15
// baseline (speedup 1.0000x reference)
#include <cuda_runtime.h>
#include <cuda_fp16.h>
#include <cstdint>

// ---------------------------------------------------------------------------
// MLPEdgeUpdator via mma.sync.m16n8k16.f16 (compute_103 target: no tcgen05).
//
// C[E,256] = concat(edge_feat | node_feat[src_idx] | edge_query)[E,384]
//            @ [W_feat | W_query][384,256] + [b_feat | b_query]
//
// R9: phase-overlap restructure. B fragments for chunk j+1 are LDSM'd at the
// END of iteration j (before the barrier), overlapping the tensor pipe's
// HMMA drain — removing 2/3 of LDSM bytes from the serial post-barrier
// window. Safety: fill for chunk j+1 was issued early at iter j-2 and each
// thread's cp.async.wait_group 1 at end of iter j-1 + barrier j orders all
// threads' fills before any trailing ldsm at iter j.
// 512 threads, 4x4 warp grid, warp tile 32x64, K = 12 x 32 chunks.
// A: LDG -> reg fp16 convert -> swizzled STS (double-buffered tile).
// B: pre-swizzled fp16 weight image, 4-stage cp.async ring, fill issued
// early in the iteration (distance 3). ONE __syncthreads per chunk.
// ---------------------------------------------------------------------------

constexpr int DIMV   = 128;
constexpr int MTILE  = 128;
constexpr int KCH    = 32;
constexpr int NCHUNK = 12;
constexpr int THREADS = 512;

constexpr int A16_BYTES = MTILE * KCH * 2;         // 8192 (per buffer)
constexpr int B16_BYTES = 256 * KCH * 2;           // 16384 (per stage)
constexpr int OFF_IDX  = 0;                        // 128 x int32
constexpr int OFF_BIAS = 512;                      // 256 x fp32
constexpr int OFF_A16  = 2048;                     // 2 buffers
constexpr int OFF_B    = OFF_A16 + 2 * A16_BYTES;  // 18432, 4 stages
constexpr int SMEM_TOTAL = OFF_B + 4 * B16_BYTES;  // 83968

// Pre-swizzled fp16 B image: 12 chunks x 256 n-rows x 32 k
__device__ __half g_Bimg[NCHUNK * 256 * KCH];
__device__ int g_idx_is64;

__device__ __forceinline__ uint32_t smem_u32(const void* p) {
    uint32_t a;
    asm("{ .reg .u64 t; cvta.to.shared.u64 t, %1; cvt.u32.u64 %0, t; }"
        : "=r"(a) : "l"(p));
    return a;
}

__device__ __forceinline__ void cp_async16(uint32_t dst, const void* src) {
    asm volatile("cp.async.cg.shared.global [%0], [%1], 16;"
                 :: "r"(dst), "l"(src));
}
#define CP_COMMIT() asm volatile("cp.async.commit_group;")
#define CP_WAIT1()  asm volatile("cp.async.wait_group 1;")
#define CP_WAIT2()  asm volatile("cp.async.wait_group 2;")

__device__ __forceinline__ void ldsm4(uint32_t* r, uint32_t addr) {
    asm volatile("ldmatrix.sync.aligned.m8n8.x4.shared.b16 {%0,%1,%2,%3}, [%4];"
                 : "=r"(r[0]), "=r"(r[1]), "=r"(r[2]), "=r"(r[3]) : "r"(addr));
}

__device__ __forceinline__ void mma_f16(float* d, const uint32_t* a,
                                        uint32_t b0, uint32_t b1) {
    asm volatile(
        "mma.sync.aligned.m16n8k16.row.col.f32.f16.f16.f32 "
        "{%0,%1,%2,%3}, {%4,%5,%6,%7}, {%8,%9}, {%0,%1,%2,%3};"
        : "+f"(d[0]), "+f"(d[1]), "+f"(d[2]), "+f"(d[3])
        : "r"(a[0]), "r"(a[1]), "r"(a[2]), "r"(a[3]), "r"(b0), "r"(b1));
}

__device__ __forceinline__ uint32_t pack_h2(float lo, float hi) {
    __half2 h = __floats2half2_rn(lo, hi);
    return *(uint32_t*)&h;
}

// --------- prep: fp16 swizzled B image + idx width detection ---------------
__global__ void prep_kernel(const float* __restrict__ Wf,
                            const float* __restrict__ Wq,
                            const unsigned int* __restrict__ idx_raw) {
    int t = blockIdx.x * blockDim.x + threadIdx.x;   // 0..98303
    int n = t & 255;
    int kk = (t >> 8) & 31;
    int j = t >> 13;
    float v = (n < DIMV) ? Wf[(size_t)(j * KCH + kk) * DIMV + n]
                         : Wq[(size_t)(j * KCH + kk) * DIMV + (n - DIMV)];
    int swc = (kk >> 3) ^ ((n >> 1) & 3);
    g_Bimg[j * 8192 + n * 32 + swc * 8 + (kk & 7)] = __float2half_rn(v);

    if (t == 0) {
        int is64 = 1;
        #pragma unroll
        for (int i = 0; i < 8; i++)
            if (idx_raw[2 * i + 1] != 0u) is64 = 0;
        g_idx_is64 = is64;
    }
}

// A: each thread owns 32B fp32 of the chunk: LDG to regs.
__device__ __forceinline__ void load_A(
    int j, int tid, int row0, int E, const int* sidx,
    const float* __restrict__ ef, const float* __restrict__ eq,
    const float* __restrict__ nf, float4* fA) {
    int r = tid >> 2;                 // row 0..127
    int q = tid & 3;                  // 32B group within row
    int e = row0 + r;
    if (e >= E) e = E - 1;
    const float* src;
    if (j < 4)       src = ef + (size_t)e * DIMV + j * 32;
    else if (j < 8)  src = nf + (size_t)sidx[r] * DIMV + (j - 4) * 32;
    else             src = eq + (size_t)e * DIMV + (j - 8) * 32;
    src += q * 8;
    fA[0] = *(const float4*)src;
    fA[1] = *(const float4*)(src + 4);
}

// B: straight 16B copy of pre-swizzled fp16 image (L2-hot).
__device__ __forceinline__ void fill_B(int j, uint32_t stB, int tid) {
    const char* bsrc = (const char*)g_Bimg + (size_t)j * B16_BYTES;
    #pragma unroll
    for (int i = 0; i < 2; i++) {
        int id = tid + i * THREADS;   // 0..1023
        cp_async16(stB + (uint32_t)(id * 16), bsrc + (size_t)id * 16);
    }
}

__global__ void __launch_bounds__(THREADS, 1)
mlp_edge_kernel(const float* __restrict__ edge_feat,
                const float* __restrict__ edge_query,
                const float* __restrict__ node_feat,
                const void* __restrict__ src_idx,
                const float* __restrict__ b_feat,
                const float* __restrict__ b_query,
                float* __restrict__ out, int E) {
    extern __shared__ char smem[];
    const uint32_t sb = smem_u32(smem);
    const int tid = threadIdx.x;
    const int lane = tid & 31;
    const int wid = tid >> 5;
    const int warpM = wid >> 2;   // 0..3 (32-row slabs)
    const int warpN = wid & 3;    // 0..3 (64-col slabs)
    const int row0 = blockIdx.x * MTILE;
    const int is64 = g_idx_is64;

    if (tid < 128) {
        int e = row0 + tid;
        if (e >= E) e = E - 1;
        int v = is64 ? (int)((const long long*)src_idx)[e]
                     : ((const int*)src_idx)[e];
        ((int*)(smem + OFF_IDX))[tid] = v;
    } else if (tid < 384) {
        int c = tid - 128;
        ((float*)(smem + OFF_BIAS))[c] = (c < DIMV) ? b_feat[c] : b_query[c - DIMV];
    }
    __syncthreads();
    const int* sidx = (const int*)(smem + OFF_IDX);

    // prologue: A chunk 0 into regs; B chunks 0..2 in flight (stages 0..2)
    float4 fA[2];
    load_A(0, tid, row0, E, sidx, edge_feat, edge_query, node_feat, fA);
    #pragma unroll
    for (int j = 0; j < 3; j++) {
        fill_B(j, sb + OFF_B + j * B16_BYTES, tid);
        CP_COMMIT();
    }

    float acc[2][8][4];
    #pragma unroll
    for (int mt = 0; mt < 2; mt++)
        #pragma unroll
        for (int nt = 0; nt < 8; nt++)
            #pragma unroll
            for (int q = 0; q < 4; q++) acc[mt][nt][q] = 0.f;

    // ldmatrix lane bases (m16n8k16 quadrant ordering)
    const int mrow = warpM * 32 + ((lane >> 3) & 1) * 8 + (lane & 7);
    const int cA = lane >> 4;
    const int swA = (mrow >> 1) & 3;        // invariant under +16
    const int nrow = warpN * 64 + (lane >> 4) * 8 + (lane & 7);
    const int cB = (lane >> 3) & 1;
    const int swB = (nrow >> 1) & 3;

    // A STS per-thread address (fixed across chunks, modulo buffer select)
    const int ra = tid >> 2, qa = tid & 3;
    const uint32_t stsA =
        (uint32_t)(OFF_A16 + ra * 64 + ((qa ^ ((ra >> 1) & 3)) << 4));

    // carried B fragments for the CURRENT chunk (both k16 steps)
    uint32_t bfr[2][4][4];

    for (int j = 0; j < NCHUNK; j++) {
        const uint32_t stB = sb + OFF_B + (j & 3) * B16_BYTES;
        const uint32_t abuf = (uint32_t)((j & 1) * A16_BYTES);

        // regs (chunk j) -> swizzled fp16 A tile, buffer j&1
        {
            uint4 h;
            h.x = pack_h2(fA[0].x, fA[0].y);
            h.y = pack_h2(fA[0].z, fA[0].w);
            h.z = pack_h2(fA[1].x, fA[1].y);
            h.w = pack_h2(fA[1].z, fA[1].w);
            *(uint4*)(smem + stsA + abuf) = h;
        }
        if (j == 0) CP_WAIT2();           // own chunk-0 fills complete
        __syncthreads();                  // A(j) visible; orders B fills too

        if (j == 0) {
            // one-time serial load of chunk 0's B fragments
            #pragma unroll
            for (int step = 0; step < 2; step++)
                #pragma unroll
                for (int nt2 = 0; nt2 < 4; nt2++)
                    ldsm4(bfr[step][nt2],
                          stB + (uint32_t)((nrow + nt2 * 16) * 64 +
                                (((step * 2 + cB) ^ swB) << 4)));
        }

        // early B fill for chunk j+3 (stage (j+3)&3 == (j-1)&3, readers done)
        if (j + 3 < NCHUNK)
            fill_B(j + 3, sb + OFF_B + ((j + 3) & 3) * B16_BYTES, tid);
        CP_COMMIT();                      // unconditional: wait arithmetic

        // A LDG prefetch for chunk j+1
        if (j + 1 < NCHUNK)
            load_A(j + 1, tid, row0, E, sidx,
                   edge_feat, edge_query, node_feat, fA);

        // compute: A fragments fresh, B fragments carried
        #pragma unroll
        for (int step = 0; step < 2; step++) {
            uint32_t a[2][4];
            #pragma unroll
            for (int mt = 0; mt < 2; mt++) {
                uint32_t addr = sb + abuf +
                    (uint32_t)(OFF_A16 + (mrow + mt * 16) * 64 +
                               (((step * 2 + cA) ^ swA) << 4));
                ldsm4(a[mt], addr);
            }
            #pragma unroll
            for (int mt = 0; mt < 2; mt++)
                #pragma unroll
                for (int nt = 0; nt < 8; nt++)
                    mma_f16(acc[mt][nt], a[mt],
                            bfr[step][nt >> 1][(nt & 1) * 2],
                            bfr[step][nt >> 1][(nt & 1) * 2 + 1]);
        }

        // trailing: B fragments for chunk j+1 — crossbar work overlapping
        // the tensor pipe's HMMA drain. Own wait_group 1 (only the fill
        // just issued may be pending -> chunk j+1 guaranteed); cross-thread
        // visibility came from every thread's wait at iter j-1 + barrier j.
        if (j + 1 < NCHUNK) {
            CP_WAIT1();
            const uint32_t stBn = sb + OFF_B + ((j + 1) & 3) * B16_BYTES;
            #pragma unroll
            for (int step = 0; step < 2; step++)
                #pragma unroll
                for (int nt2 = 0; nt2 < 4; nt2++)
                    ldsm4(bfr[step][nt2],
                          stBn + (uint32_t)((nrow + nt2 * 16) * 64 +
                                 (((step * 2 + cB) ^ swB) << 4)));
        }
    }

    // ---- epilogue: bias add + store (feat half | query half) ----
    const float* bias = (const float*)(smem + OFF_BIAS);
    const int g = lane >> 2;
    const int tg = lane & 3;
    const int half = warpN >> 1;
    float* outh = out + (size_t)half * (size_t)E * DIMV;
    const float* biash = bias + half * DIMV;

    #pragma unroll
    for (int mt = 0; mt < 2; mt++) {
        const int rbase = warpM * 32 + mt * 16 + g;
        #pragma unroll
        for (int dr = 0; dr < 2; dr++) {
            const int e = row0 + rbase + dr * 8;
            if (e < E) {
                float* orow = outh + (size_t)e * DIMV;
                #pragma unroll
                for (int nt = 0; nt < 8; nt++) {
                    const int col = (warpN & 1) * 64 + nt * 8 + tg * 2;
                    float2 v;
                    v.x = acc[mt][nt][dr * 2 + 0] + biash[col];
                    v.y = acc[mt][nt][dr * 2 + 1] + biash[col + 1];
                    *(float2*)(orow + col) = v;
                }
            }
        }
    }
}

// ------------------------- launch -------------------------------------------
extern "C" void kernel_launch(void* const* d_in, const int* in_sizes, int n_in,
                              void* d_out, int out_size) {
    const float* edge_feat  = (const float*)d_in[0];
    const float* edge_query = (const float*)d_in[1];
    const float* node_feat  = (const float*)d_in[2];
    const void*  src_idx    = d_in[3];
    const float* W_feat     = (const float*)d_in[4];
    const float* b_feat     = (const float*)d_in[5];
    const float* W_query    = (const float*)d_in[6];
    const float* b_query    = (const float*)d_in[7];
    const int E = in_sizes[0] / DIMV;

    prep_kernel<<<NCHUNK * 256 * KCH / 256, 256>>>(
        W_feat, W_query, (const unsigned int*)src_idx);

    static int configured = -1;
    if (configured < 0) {
        cudaFuncSetAttribute(mlp_edge_kernel,
                             cudaFuncAttributeMaxDynamicSharedMemorySize,
                             SMEM_TOTAL);
        configured = 1;
    }
    const int grid = (E + MTILE - 1) / MTILE;
    mlp_edge_kernel<<<grid, THREADS, SMEM_TOTAL>>>(
        edge_feat, edge_query, node_feat, src_idx,
        b_feat, b_query, (float*)d_out, E);
}

// round 17
// speedup vs baseline: 1.1891x; 1.1891x over previous
#include <cuda_runtime.h>
#include <cuda_fp16.h>
#include <cstdint>

// ---------------------------------------------------------------------------
// MLPEdgeUpdator via mma.sync.m16n8k16.f16 (compute_103 target: no tcgen05).
//
// C[E,256] = concat(edge_feat | node_feat[src_idx] | edge_query)[E,384]
//            @ [W_feat | W_query][384,256] + [b_feat | b_query]
//
// R10: TWO CTAs per SM (M=64 tile, 256 threads, 8 warps each) = two
// independent barrier domains. While one CTA sits in its post-barrier LDSM
// phase the other drives HMMA — the phase overlap that ILP (R7/R9, register
// wall) and more same-CTA warps (R8, same barrier) could not provide.
// Loop structure identical to R8: one __syncthreads per chunk, A direct
// LDG->reg convert->swizzled STS (double-buffered), B 4-stage cp.async ring
// from pre-swizzled fp16 weight image, prefetch distance 3.
// ---------------------------------------------------------------------------

constexpr int DIMV   = 128;
constexpr int MTILE  = 64;
constexpr int KCH    = 32;
constexpr int NCHUNK = 12;
constexpr int THREADS = 256;

constexpr int A16_BYTES = MTILE * KCH * 2;         // 4096 (per buffer)
constexpr int B16_BYTES = 256 * KCH * 2;           // 16384 (per stage)
constexpr int OFF_IDX  = 0;                        // 64 x int32
constexpr int OFF_BIAS = 512;                      // 256 x fp32
constexpr int OFF_A16  = 2048;                     // 2 buffers
constexpr int OFF_B    = OFF_A16 + 2 * A16_BYTES;  // 10240, 4 stages
constexpr int SMEM_TOTAL = OFF_B + 4 * B16_BYTES;  // 75776 (x2 CTAs = 148K)

// Pre-swizzled fp16 B image: 12 chunks x 256 n-rows x 32 k
__device__ __half g_Bimg[NCHUNK * 256 * KCH];
__device__ int g_idx_is64;

__device__ __forceinline__ uint32_t smem_u32(const void* p) {
    uint32_t a;
    asm("{ .reg .u64 t; cvta.to.shared.u64 t, %1; cvt.u32.u64 %0, t; }"
        : "=r"(a) : "l"(p));
    return a;
}

__device__ __forceinline__ void cp_async16(uint32_t dst, const void* src) {
    asm volatile("cp.async.cg.shared.global [%0], [%1], 16;"
                 :: "r"(dst), "l"(src));
}
#define CP_COMMIT() asm volatile("cp.async.commit_group;")
#define CP_WAIT2()  asm volatile("cp.async.wait_group 2;")

__device__ __forceinline__ void ldsm4(uint32_t* r, uint32_t addr) {
    asm volatile("ldmatrix.sync.aligned.m8n8.x4.shared.b16 {%0,%1,%2,%3}, [%4];"
                 : "=r"(r[0]), "=r"(r[1]), "=r"(r[2]), "=r"(r[3]) : "r"(addr));
}

__device__ __forceinline__ void mma_f16(float* d, const uint32_t* a,
                                        uint32_t b0, uint32_t b1) {
    asm volatile(
        "mma.sync.aligned.m16n8k16.row.col.f32.f16.f16.f32 "
        "{%0,%1,%2,%3}, {%4,%5,%6,%7}, {%8,%9}, {%0,%1,%2,%3};"
        : "+f"(d[0]), "+f"(d[1]), "+f"(d[2]), "+f"(d[3])
        : "r"(a[0]), "r"(a[1]), "r"(a[2]), "r"(a[3]), "r"(b0), "r"(b1));
}

__device__ __forceinline__ uint32_t pack_h2(float lo, float hi) {
    __half2 h = __floats2half2_rn(lo, hi);
    return *(uint32_t*)&h;
}

// --------- prep: fp16 swizzled B image + idx width detection ---------------
__global__ void prep_kernel(const float* __restrict__ Wf,
                            const float* __restrict__ Wq,
                            const unsigned int* __restrict__ idx_raw) {
    int t = blockIdx.x * blockDim.x + threadIdx.x;   // 0..98303
    int n = t & 255;
    int kk = (t >> 8) & 31;
    int j = t >> 13;
    float v = (n < DIMV) ? Wf[(size_t)(j * KCH + kk) * DIMV + n]
                         : Wq[(size_t)(j * KCH + kk) * DIMV + (n - DIMV)];
    int swc = (kk >> 3) ^ ((n >> 1) & 3);
    g_Bimg[j * 8192 + n * 32 + swc * 8 + (kk & 7)] = __float2half_rn(v);

    if (t == 0) {
        int is64 = 1;
        #pragma unroll
        for (int i = 0; i < 8; i++)
            if (idx_raw[2 * i + 1] != 0u) is64 = 0;
        g_idx_is64 = is64;
    }
}

// A: 64 rows x 32 fp32 = 8 KB; each of 256 threads owns 32B: LDG to regs.
__device__ __forceinline__ void load_A(
    int j, int tid, int row0, int E, const int* sidx,
    const float* __restrict__ ef, const float* __restrict__ eq,
    const float* __restrict__ nf, float4* fA) {
    int r = tid >> 2;                 // row 0..63
    int q = tid & 3;                  // 32B group within row
    int e = row0 + r;
    if (e >= E) e = E - 1;
    const float* src;
    if (j < 4)       src = ef + (size_t)e * DIMV + j * 32;
    else if (j < 8)  src = nf + (size_t)sidx[r] * DIMV + (j - 4) * 32;
    else             src = eq + (size_t)e * DIMV + (j - 8) * 32;
    src += q * 8;
    fA[0] = *(const float4*)src;
    fA[1] = *(const float4*)(src + 4);
}

// B: straight 16B copy of pre-swizzled fp16 image (L2-hot).
__device__ __forceinline__ void fill_B(int j, uint32_t stB, int tid) {
    const char* bsrc = (const char*)g_Bimg + (size_t)j * B16_BYTES;
    #pragma unroll
    for (int i = 0; i < 4; i++) {
        int id = tid + i * THREADS;   // 0..1023
        cp_async16(stB + (uint32_t)(id * 16), bsrc + (size_t)id * 16);
    }
}

__global__ void __launch_bounds__(THREADS, 2)
mlp_edge_kernel(const float* __restrict__ edge_feat,
                const float* __restrict__ edge_query,
                const float* __restrict__ node_feat,
                const void* __restrict__ src_idx,
                const float* __restrict__ b_feat,
                const float* __restrict__ b_query,
                float* __restrict__ out, int E) {
    extern __shared__ char smem[];
    const uint32_t sb = smem_u32(smem);
    const int tid = threadIdx.x;
    const int lane = tid & 31;
    const int wid = tid >> 5;
    const int warpM = wid >> 2;   // 0..1 (32-row slabs)
    const int warpN = wid & 3;    // 0..3 (64-col slabs)
    const int row0 = blockIdx.x * MTILE;
    const int is64 = g_idx_is64;

    if (tid < 64) {
        int e = row0 + tid;
        if (e >= E) e = E - 1;
        int v = is64 ? (int)((const long long*)src_idx)[e]
                     : ((const int*)src_idx)[e];
        ((int*)(smem + OFF_IDX))[tid] = v;
    }
    ((float*)(smem + OFF_BIAS))[tid] =
        (tid < DIMV) ? b_feat[tid] : b_query[tid - DIMV];
    __syncthreads();
    const int* sidx = (const int*)(smem + OFF_IDX);

    // prologue: A chunk 0 into regs; B chunks 0..2 in flight (stages 0..2)
    float4 fA[2];
    load_A(0, tid, row0, E, sidx, edge_feat, edge_query, node_feat, fA);
    #pragma unroll
    for (int j = 0; j < 3; j++) {
        fill_B(j, sb + OFF_B + j * B16_BYTES, tid);
        CP_COMMIT();
    }

    float acc[2][8][4];
    #pragma unroll
    for (int mt = 0; mt < 2; mt++)
        #pragma unroll
        for (int nt = 0; nt < 8; nt++)
            #pragma unroll
            for (int q = 0; q < 4; q++) acc[mt][nt][q] = 0.f;

    // ldmatrix lane bases (m16n8k16 quadrant ordering)
    const int mrow = warpM * 32 + ((lane >> 3) & 1) * 8 + (lane & 7);
    const int cA = lane >> 4;
    const int swA = (mrow >> 1) & 3;        // invariant under +16
    const int nrow = warpN * 64 + (lane >> 4) * 8 + (lane & 7);
    const int cB = (lane >> 3) & 1;
    const int swB = (nrow >> 1) & 3;

    // A STS per-thread address (fixed across chunks, modulo buffer select)
    const int ra = tid >> 2, qa = tid & 3;
    const uint32_t stsA =
        (uint32_t)(OFF_A16 + ra * 64 + ((qa ^ ((ra >> 1) & 3)) << 4));

    for (int j = 0; j < NCHUNK; j++) {
        const uint32_t stB = sb + OFF_B + (j & 3) * B16_BYTES;
        const uint32_t abuf = (uint32_t)((j & 1) * A16_BYTES);
        CP_WAIT2();                       // B chunk j landed

        // regs (chunk j) -> swizzled fp16 A tile, buffer j&1
        {
            uint4 h;
            h.x = pack_h2(fA[0].x, fA[0].y);
            h.y = pack_h2(fA[0].z, fA[0].w);
            h.z = pack_h2(fA[1].x, fA[1].y);
            h.w = pack_h2(fA[1].z, fA[1].w);
            *(uint4*)(smem + stsA + abuf) = h;
        }
        __syncthreads();                  // the ONLY barrier in the chunk

        // overlap work: A LDGs for j+1, B cp.async for j+3 (stage (j+3)&3
        // == (j-1)&3, whose readers all passed the barrier above)
        if (j + 1 < NCHUNK)
            load_A(j + 1, tid, row0, E, sidx,
                   edge_feat, edge_query, node_feat, fA);
        if (j + 3 < NCHUNK)
            fill_B(j + 3, sb + OFF_B + ((j + 3) & 3) * B16_BYTES, tid);
        CP_COMMIT();                      // unconditional: wait arithmetic

        #pragma unroll
        for (int step = 0; step < 2; step++) {
            uint32_t a[2][4], b[4][4];
            #pragma unroll
            for (int mt = 0; mt < 2; mt++) {
                uint32_t addr = sb + abuf +
                    (uint32_t)(OFF_A16 + (mrow + mt * 16) * 64 +
                               (((step * 2 + cA) ^ swA) << 4));
                ldsm4(a[mt], addr);
            }
            #pragma unroll
            for (int nt2 = 0; nt2 < 4; nt2++) {
                uint32_t addr = stB + (uint32_t)((nrow + nt2 * 16) * 64 +
                                (((step * 2 + cB) ^ swB) << 4));
                ldsm4(b[nt2], addr);
            }
            #pragma unroll
            for (int mt = 0; mt < 2; mt++)
                #pragma unroll
                for (int nt = 0; nt < 8; nt++)
                    mma_f16(acc[mt][nt], a[mt],
                            b[nt >> 1][(nt & 1) * 2],
                            b[nt >> 1][(nt & 1) * 2 + 1]);
        }
        // no trailing barrier: next iteration's STS targets the other A
        // buffer; its barrier orders everything else.
    }

    // ---- epilogue: bias add + store (feat half | query half) ----
    const float* bias = (const float*)(smem + OFF_BIAS);
    const int g = lane >> 2;
    const int tg = lane & 3;
    const int half = warpN >> 1;
    float* outh = out + (size_t)half * (size_t)E * DIMV;
    const float* biash = bias + half * DIMV;

    #pragma unroll
    for (int mt = 0; mt < 2; mt++) {
        const int rbase = warpM * 32 + mt * 16 + g;
        #pragma unroll
        for (int dr = 0; dr < 2; dr++) {
            const int e = row0 + rbase + dr * 8;
            if (e < E) {
                float* orow = outh + (size_t)e * DIMV;
                #pragma unroll
                for (int nt = 0; nt < 8; nt++) {
                    const int col = (warpN & 1) * 64 + nt * 8 + tg * 2;
                    float2 v;
                    v.x = acc[mt][nt][dr * 2 + 0] + biash[col];
                    v.y = acc[mt][nt][dr * 2 + 1] + biash[col + 1];
                    *(float2*)(orow + col) = v;
                }
            }
        }
    }
}

// ------------------------- launch -------------------------------------------
extern "C" void kernel_launch(void* const* d_in, const int* in_sizes, int n_in,
                              void* d_out, int out_size) {
    const float* edge_feat  = (const float*)d_in[0];
    const float* edge_query = (const float*)d_in[1];
    const float* node_feat  = (const float*)d_in[2];
    const void*  src_idx    = d_in[3];
    const float* W_feat     = (const float*)d_in[4];
    const float* b_feat     = (const float*)d_in[5];
    const float* W_query    = (const float*)d_in[6];
    const float* b_query    = (const float*)d_in[7];
    const int E = in_sizes[0] / DIMV;

    prep_kernel<<<NCHUNK * 256 * KCH / 256, 256>>>(
        W_feat, W_query, (const unsigned int*)src_idx);

    static int configured = -1;
    if (configured < 0) {
        cudaFuncSetAttribute(mlp_edge_kernel,
                             cudaFuncAttributeMaxDynamicSharedMemorySize,
                             SMEM_TOTAL);
        configured = 1;
    }
    const int grid = (E + MTILE - 1) / MTILE;
    mlp_edge_kernel<<<grid, THREADS, SMEM_TOTAL>>>(
        edge_feat, edge_query, node_feat, src_idx,
        b_feat, b_query, (float*)d_out, E);
}